// round 12
// baseline (speedup 1.0000x reference)
#include <cuda_runtime.h>
#include <cuda_fp16.h>
#include <stdint.h>
#include <math.h>

typedef unsigned int u32;

#define C_DIM 512
#define N_DIM 4096
#define MAXB  4

// -------- scratch (__device__ globals) --------------------------------------
__device__ __half g_xs[MAXB * C_DIM * N_DIM];   // xn single fp16
__device__ __half g_qs[MAXB * C_DIM * N_DIM];   // q single fp16
__device__ __half g_ks[MAXB * C_DIM * N_DIM];   // k single fp16
__device__ __half g_vs[MAXB * C_DIM * N_DIM];   // v single fp16
__device__ __half g_vps[MAXB * C_DIM * N_DIM];  // V' = Wp.v single fp16
__device__ __half g_wh[4 * C_DIM * C_DIM];      // weights hi (q,k,v,p stacked)
__device__ __half g_wl[4 * C_DIM * C_DIM];      // weights lo
__device__ __half g_attn[MAXB * (size_t)N_DIM * N_DIM];  // S fp16 (134 MB)
__device__ __half g_ps[MAXB * (size_t)N_DIM * N_DIM];    // P fp16 (134 MB)

// ============================================================================
// Helpers
// ============================================================================
__device__ __forceinline__ void split_store2(__half* Ch, __half* Cl,
                                             size_t o, float x, float y)
{
    __half hx = __float2half(x);
    __half hy = __float2half(y);
    __half lx = __float2half(x - __half2float(hx));
    __half ly = __float2half(y - __half2float(hy));
    __half2 th(hx, hy);
    __half2 tl(lx, ly);
    *(u32*)&Ch[o] = *(u32*)&th;
    *(u32*)&Cl[o] = *(u32*)&tl;
}

__device__ __forceinline__ void single_store2(__half* C, size_t o, float x, float y)
{
    __half2 t(__float2half(x), __float2half(y));
    *(u32*)&C[o] = *(u32*)&t;
}

__device__ __forceinline__ u32 saddr(const void* p)
{
    return (u32)__cvta_generic_to_shared(p);
}

__device__ __forceinline__ void cp16(u32 dst, const void* src)
{
    asm volatile("cp.async.cg.shared.global [%0], [%1], 16;\n" :: "r"(dst), "l"(src));
}
__device__ __forceinline__ void cp_commit()
{
    asm volatile("cp.async.commit_group;\n");
}
template <int NN_>
__device__ __forceinline__ void cp_wait()
{
    asm volatile("cp.async.wait_group %0;\n" :: "n"(NN_));
}

__device__ __forceinline__ void ldsm4(u32* r, u32 a)
{
    asm volatile("ldmatrix.sync.aligned.m8n8.x4.shared.b16 {%0,%1,%2,%3}, [%4];\n"
        : "=r"(r[0]), "=r"(r[1]), "=r"(r[2]), "=r"(r[3]) : "r"(a));
}
__device__ __forceinline__ void ldsm4t(u32* r, u32 a)
{
    asm volatile("ldmatrix.sync.aligned.m8n8.x4.trans.shared.b16 {%0,%1,%2,%3}, [%4];\n"
        : "=r"(r[0]), "=r"(r[1]), "=r"(r[2]), "=r"(r[3]) : "r"(a));
}
__device__ __forceinline__ void mma_f16(float* c, const u32* a, u32 b0, u32 b1)
{
    asm volatile(
        "mma.sync.aligned.m16n8k16.row.col.f32.f16.f16.f32 "
        "{%0,%1,%2,%3}, {%4,%5,%6,%7}, {%8,%9}, {%0,%1,%2,%3};\n"
        : "+f"(c[0]), "+f"(c[1]), "+f"(c[2]), "+f"(c[3])
        : "r"(a[0]), "r"(a[1]), "r"(a[2]), "r"(a[3]), "r"(b0), "r"(b1));
}

// ============================================================================
// fp32 -> split fp16, all 4 weight matrices in one launch (grid.y = matrix)
// ============================================================================
__global__ void split4_kernel(const float* __restrict__ wq,
                              const float* __restrict__ wk,
                              const float* __restrict__ wv,
                              const float* __restrict__ wp,
                              __half* __restrict__ h,
                              __half* __restrict__ l, int n4)
{
    int i = blockIdx.x * blockDim.x + threadIdx.x;
    if (i >= n4) return;
    int sel = blockIdx.y;
    const float* in = (sel == 0) ? wq : (sel == 1) ? wk : (sel == 2) ? wv : wp;
    size_t off = (size_t)sel * n4 * 4;
    float4 v = ((const float4*)in)[i];
    split_store2(h + off, l + off, (size_t)i * 4,     v.x, v.y);
    split_store2(h + off, l + off, (size_t)i * 4 + 2, v.z, v.w);
}

// ============================================================================
// GroupNorm: 32 groups, 16 ch/group, eps=1e-5; writes single fp16
// ============================================================================
__global__ void groupnorm_kernel(const float* __restrict__ x,
                                 const float* __restrict__ w,
                                 const float* __restrict__ b,
                                 __half* __restrict__ os)
{
    const int CPG = 16;
    const int CNT = CPG * N_DIM;
    int bg = blockIdx.x;
    int g  = bg & 31;
    int bb = bg >> 5;
    size_t base = ((size_t)bb * C_DIM + (size_t)g * CPG) * N_DIM;
    const float4* x4 = (const float4*)(x + base);
    int tid = threadIdx.x;

    float s = 0.f, ss = 0.f;
    for (int i = tid; i < CNT / 4; i += blockDim.x) {
        float4 v = x4[i];
        s  += v.x + v.y + v.z + v.w;
        ss += v.x * v.x + v.y * v.y + v.z * v.z + v.w * v.w;
    }
    __shared__ float rs[8], rss[8];
    #pragma unroll
    for (int o = 16; o; o >>= 1) {
        s  += __shfl_xor_sync(0xffffffffu, s,  o);
        ss += __shfl_xor_sync(0xffffffffu, ss, o);
    }
    int wid = tid >> 5;
    int lid = tid & 31;
    if (lid == 0) { rs[wid] = s; rss[wid] = ss; }
    __syncthreads();
    if (tid == 0) {
        float ts = 0.f, tss = 0.f;
        int nw = blockDim.x >> 5;
        for (int i = 0; i < nw; i++) { ts += rs[i]; tss += rss[i]; }
        rs[0] = ts; rss[0] = tss;
    }
    __syncthreads();
    float mu   = rs[0] / (float)CNT;
    float var  = rss[0] / (float)CNT - mu * mu;
    float rsig = rsqrtf(var + 1e-5f);

    for (int i = tid; i < CNT / 4; i += blockDim.x) {
        int c = g * CPG + (i >> 10);
        float sc = w[c] * rsig;
        float sh = b[c] - mu * sc;
        float4 v = x4[i];
        size_t o = base + (size_t)i * 4;
        single_store2(os, o,     v.x * sc + sh, v.y * sc + sh);
        single_store2(os, o + 2, v.z * sc + sh, v.w * sc + sh);
    }
}

// ============================================================================
// Pipelined fp16 tensor-core GEMM (cp.async, NST stages, 2 CTAs/SM).
//   C[m,n] = alpha * sum_k A(m,k)*B(k,n)
//   ASP/BSP: operand has a lo compensation term (adds 1 MMA each).
//   TA/TB: storage orientation. BK: 32 or 64. NST: pipeline stages.
//   OMODE: 0 = fp32 out (+row bias, +res)
//          1 = single fp16 out (Ch) (+row bias)
//          2 = fused-QKV routing (blockIdx.y: 0-3=q,4-7=k,8-11=v; single out)
// 1-term instantiations (ASP+BSP==0) use register double-buffered fragments
// (ldsm for ks+1 issued before MMAs of ks) to hide smem latency.
// Conflict-free smem strides: narrow rows 56 (BK32) / 72 (BK64); wide rows 136.
// ============================================================================
template <bool TA, bool TB, int ASP, int BSP, int OMODE, int BK, int NST>
__global__ __launch_bounds__(256, 2)
void pgemm_kernel(const __half* __restrict__ Agh,
                  const __half* __restrict__ Agl,
                  const __half* __restrict__ Bgh,
                  const __half* __restrict__ Bgl,
                  float* __restrict__ Cf,
                  __half* __restrict__ Ch,
                  __half* __restrict__ Qs,
                  __half* __restrict__ Ks,
                  __half* __restrict__ Vs,
                  int K, int lda, int ldb, int ldc,
                  long long sA, long long sB, long long sC,
                  const float* __restrict__ bias,
                  const float* __restrict__ bias2,
                  const float* __restrict__ bias3,
                  const float* __restrict__ res, long long sRes,
                  float alpha)
{
    const int PAD = (BK == 32) ? 56 : (BK + 8);
    const int AST = TA ? 136 : PAD;
    const int BST = TB ? PAD : 136;
    const int ASZ = TA ? (BK * AST) : (128 * AST);
    const int BSZ = TB ? (128 * BST) : (BK * BST);
    const int STAGE = (1 + ASP) * ASZ + (1 + BSP) * BSZ;
    const int KD = BK / 8;
    const int RIT = BK / 16;
    const int NKS = BK / 16;
    const bool DB = (ASP == 0 && BSP == 0);

    extern __shared__ __align__(16) char smraw[];
    __half* sm = (__half*)smraw;

    int z = blockIdx.z;
    Agh += (long long)z * sA;
    if (ASP) Agl += (long long)z * sA;
    Bgh += (long long)z * sB;
    if (BSP) Bgl += (long long)z * sB;

    int sel = 0;
    int m0;
    if (OMODE == 2) {
        sel = blockIdx.y >> 2;
        m0  = (blockIdx.y & 3) * 128;
        long long wo = (long long)sel * C_DIM * C_DIM;
        Agh += wo;
        if (ASP) Agl += wo;
        Qs += (long long)z * sC;
        Ks += (long long)z * sC;
        Vs += (long long)z * sC;
    } else {
        m0 = blockIdx.y * 128;
        if (OMODE == 1) Ch += (long long)z * sC;
        else            Cf += (long long)z * sC;
        if (OMODE == 0 && res) res += (long long)z * sRes;
    }

    int n0 = blockIdx.x * 128;
    int tid  = threadIdx.x;
    int lane = tid & 31;
    int wid  = tid >> 5;
    int m_w = (wid >> 2) * 64;
    int n_w = (wid & 3) * 32;

    int a_base, b_base;
    if (!TA) {
        a_base = (m_w + (lane & 15)) * AST + ((lane >> 4) * 8);
    } else {
        a_base = (((lane >> 4) & 1) * 8 + (lane & 7)) * AST
               + m_w + ((lane >> 3) & 1) * 8;
    }
    if (!TB) {
        b_base = (((lane >> 3) & 1) * 8 + (lane & 7)) * BST
               + n_w + ((lane >> 4) & 1) * 8;
    } else {
        b_base = (n_w + ((lane >> 4) & 1) * 8 + (lane & 7)) * BST
               + ((lane >> 3) & 1) * 8;
    }

    float c[4][4][4];
    #pragma unroll
    for (int i = 0; i < 4; i++) {
        #pragma unroll
        for (int j = 0; j < 4; j++) {
            #pragma unroll
            for (int t = 0; t < 4; t++) c[i][j][t] = 0.f;
        }
    }

    int KT = K / BK;

    auto load_stage = [&](int st, int k0) {
        __half* sAh = sm + st * STAGE;
        __half* sAl = sAh + ASZ;
        __half* sBh = sAh + (1 + ASP) * ASZ;
        __half* sBl = sBh + BSZ;
        #pragma unroll
        for (int r = 0; r < RIT; r++) {
            int i = tid + r * 256;
            if (!TA) {
                int m  = i / KD;
                int kq = (i % KD) * 8;
                size_t go = (size_t)(m0 + m) * lda + k0 + kq;
                int    so = m * AST + kq;
                cp16(saddr(sAh + so), Agh + go);
                if (ASP) cp16(saddr(sAl + so), Agl + go);
            } else {
                int k  = i >> 4;
                int mq = (i & 15) * 8;
                size_t go = (size_t)(k0 + k) * lda + m0 + mq;
                int    so = k * AST + mq;
                cp16(saddr(sAh + so), Agh + go);
                if (ASP) cp16(saddr(sAl + so), Agl + go);
            }
            if (!TB) {
                int k  = i >> 4;
                int nq = (i & 15) * 8;
                size_t go = (size_t)(k0 + k) * ldb + n0 + nq;
                int    so = k * BST + nq;
                cp16(saddr(sBh + so), Bgh + go);
                if (BSP) cp16(saddr(sBl + so), Bgl + go);
            } else {
                int n  = i / KD;
                int kq = (i % KD) * 8;
                size_t go = (size_t)(n0 + n) * ldb + k0 + kq;
                int    so = n * BST + kq;
                cp16(saddr(sBh + so), Bgh + go);
                if (BSP) cp16(saddr(sBl + so), Bgl + go);
            }
        }
    };

    #pragma unroll
    for (int s = 0; s < NST - 1; s++) {
        if (s < KT) load_stage(s, s * BK);
        cp_commit();
    }

    for (int kt = 0; kt < KT; kt++) {
        cp_wait<NST - 2>();
        __syncthreads();

        int pf = kt + NST - 1;
        if (pf < KT) load_stage(pf % NST, pf * BK);
        cp_commit();

        int st = kt % NST;
        const __half* pAh = sm + st * STAGE;
        const __half* pAl = pAh + ASZ;
        const __half* pBh = pAh + (1 + ASP) * ASZ;
        const __half* pBl = pBh + BSZ;

        if (DB) {
            // -------- 1-term path: register double-buffered fragments --------
            u32 ah[2][4][4], bh[2][2][4];
            auto ldfr = [&](int ks, int buf) {
                int aoff = a_base + (TA ? ks * 16 * AST : ks * 16);
                int boff = b_base + (TB ? ks * 16 : ks * 16 * BST);
                #pragma unroll
                for (int mt = 0; mt < 4; mt++) {
                    int o = aoff + (TA ? mt * 16 : mt * 16 * AST);
                    if (TA) ldsm4t(ah[buf][mt], saddr(pAh + o));
                    else    ldsm4 (ah[buf][mt], saddr(pAh + o));
                }
                #pragma unroll
                for (int p = 0; p < 2; p++) {
                    int o = boff + (TB ? p * 16 * BST : p * 16);
                    if (TB) ldsm4 (bh[buf][p], saddr(pBh + o));
                    else    ldsm4t(bh[buf][p], saddr(pBh + o));
                }
            };
            ldfr(0, 0);
            #pragma unroll
            for (int ks = 0; ks < NKS; ks++) {
                int cur = ks & 1;
                if (ks + 1 < NKS) ldfr(ks + 1, cur ^ 1);
                #pragma unroll
                for (int mt = 0; mt < 4; mt++) {
                    #pragma unroll
                    for (int nt = 0; nt < 4; nt++) {
                        int p = nt >> 1;
                        int q = (nt & 1) * 2;
                        mma_f16(c[mt][nt], ah[cur][mt],
                                bh[cur][p][q], bh[cur][p][q + 1]);
                    }
                }
            }
        } else {
            // -------- multi-term path (QKV / VP): original ordering ---------
            #pragma unroll
            for (int ks = 0; ks < NKS; ks++) {
                int aoff = a_base + (TA ? ks * 16 * AST : ks * 16);
                int boff = b_base + (TB ? ks * 16 : ks * 16 * BST);

                u32 ah[4][4], al[4][4], bh[2][4], bl[2][4];
                #pragma unroll
                for (int mt = 0; mt < 4; mt++) {
                    int o = aoff + (TA ? mt * 16 : mt * 16 * AST);
                    if (TA) {
                        ldsm4t(ah[mt], saddr(pAh + o));
                        if (ASP) ldsm4t(al[mt], saddr(pAl + o));
                    } else {
                        ldsm4(ah[mt], saddr(pAh + o));
                        if (ASP) ldsm4(al[mt], saddr(pAl + o));
                    }
                }
                #pragma unroll
                for (int p = 0; p < 2; p++) {
                    int o = boff + (TB ? p * 16 * BST : p * 16);
                    if (TB) {
                        ldsm4(bh[p], saddr(pBh + o));
                        if (BSP) ldsm4(bl[p], saddr(pBl + o));
                    } else {
                        ldsm4t(bh[p], saddr(pBh + o));
                        if (BSP) ldsm4t(bl[p], saddr(pBl + o));
                    }
                }
                #pragma unroll
                for (int mt = 0; mt < 4; mt++) {
                    #pragma unroll
                    for (int nt = 0; nt < 4; nt++) {
                        int p = nt >> 1;
                        int q = (nt & 1) * 2;
                        mma_f16(c[mt][nt], ah[mt], bh[p][q], bh[p][q + 1]);
                        if (BSP) mma_f16(c[mt][nt], ah[mt], bl[p][q], bl[p][q + 1]);
                        if (ASP) mma_f16(c[mt][nt], al[mt], bh[p][q], bh[p][q + 1]);
                    }
                }
            }
        }
        __syncthreads();
    }

    // ---- epilogue ----
    const float* bp_ = bias;
    __half* So = (OMODE == 1) ? Ch : Qs;
    if (OMODE == 2) {
        if (sel == 1)      { bp_ = bias2; So = Ks; }
        else if (sel == 2) { bp_ = bias3; So = Vs; }
    }

    int g  = lane >> 2;
    int tq = lane & 3;
    #pragma unroll
    for (int mt = 0; mt < 4; mt++) {
        int mr0 = m0 + m_w + mt * 16 + g;
        int mr1 = mr0 + 8;
        float b0v = bp_ ? bp_[mr0] : 0.f;
        float b1v = bp_ ? bp_[mr1] : 0.f;
        #pragma unroll
        for (int nt = 0; nt < 4; nt++) {
            int nc = n0 + n_w + nt * 8 + tq * 2;
            size_t o0 = (size_t)mr0 * ldc + nc;
            size_t o1 = (size_t)mr1 * ldc + nc;
            float v00 = c[mt][nt][0] * alpha + b0v;
            float v01 = c[mt][nt][1] * alpha + b0v;
            float v10 = c[mt][nt][2] * alpha + b1v;
            float v11 = c[mt][nt][3] * alpha + b1v;
            if (OMODE == 0) {
                if (res) {
                    float2 r0 = *(const float2*)&res[o0];
                    float2 r1 = *(const float2*)&res[o1];
                    v00 += r0.x; v01 += r0.y;
                    v10 += r1.x; v11 += r1.y;
                }
                float2 w0; w0.x = v00; w0.y = v01;
                float2 w1; w1.x = v10; w1.y = v11;
                *(float2*)&Cf[o0] = w0;
                *(float2*)&Cf[o1] = w1;
            } else {
                single_store2(So, o0, v00, v01);
                single_store2(So, o1, v10, v11);
            }
        }
    }
}

// ============================================================================
// Row softmax over fp16 attn[b,i,:] (4096), writes fp16 P.
// ============================================================================
__global__ void softmax_kernel(const __half* __restrict__ attn,
                               __half* __restrict__ ps)
{
    size_t row = blockIdx.x;
    const uint4* p = (const uint4*)(attn + row * N_DIM);
    uint4* q = (uint4*)(ps + row * N_DIM);
    int tid = threadIdx.x;
    __shared__ float sh[8];

    float v[2][8];
    float mx = -1e30f;
    #pragma unroll
    for (int i = 0; i < 2; i++) {
        uint4 u = p[tid + i * 256];
        u32 w[4] = {u.x, u.y, u.z, u.w};
        #pragma unroll
        for (int j = 0; j < 4; j++) {
            float2 f = __half22float2(*(__half2*)&w[j]);
            v[i][j * 2]     = f.x;
            v[i][j * 2 + 1] = f.y;
            mx = fmaxf(mx, fmaxf(f.x, f.y));
        }
    }
    #pragma unroll
    for (int o = 16; o; o >>= 1) mx = fmaxf(mx, __shfl_xor_sync(0xffffffffu, mx, o));
    if ((tid & 31) == 0) sh[tid >> 5] = mx;
    __syncthreads();
    if (tid == 0) {
        float t = sh[0];
        for (int i = 1; i < 8; i++) t = fmaxf(t, sh[i]);
        sh[0] = t;
    }
    __syncthreads();
    mx = sh[0];
    __syncthreads();

    float sum = 0.f;
    #pragma unroll
    for (int i = 0; i < 2; i++) {
        #pragma unroll
        for (int j = 0; j < 8; j++) {
            v[i][j] = __expf(v[i][j] - mx);
            sum += v[i][j];
        }
    }
    #pragma unroll
    for (int o = 16; o; o >>= 1) sum += __shfl_xor_sync(0xffffffffu, sum, o);
    if ((tid & 31) == 0) sh[tid >> 5] = sum;
    __syncthreads();
    if (tid == 0) {
        float t = 0.f;
        for (int i = 0; i < 8; i++) t += sh[i];
        sh[0] = t;
    }
    __syncthreads();
    float inv = 1.f / sh[0];

    #pragma unroll
    for (int i = 0; i < 2; i++) {
        uint4 u;
        u32* w = (u32*)&u;
        #pragma unroll
        for (int j = 0; j < 4; j++) {
            __half2 t(__float2half(v[i][j * 2] * inv),
                      __float2half(v[i][j * 2 + 1] * inv));
            w[j] = *(u32*)&t;
        }
        q[tid + i * 256] = u;
    }
}

// ============================================================================
// Host launcher
// ============================================================================
static int stage_elems(bool ta, bool tb, int asp, int bsp, int bk)
{
    int pad = (bk == 32) ? 56 : (bk + 8);
    int AST = ta ? 136 : pad;
    int BST = tb ? pad : 136;
    int ASZ = ta ? (bk * AST) : (128 * AST);
    int BSZ = tb ? (128 * BST) : (bk * BST);
    return (1 + asp) * ASZ + (1 + bsp) * BSZ;
}

extern "C" void kernel_launch(void* const* d_in, const int* in_sizes, int n_in,
                              void* d_out, int out_size)
{
    const float* x   = (const float*)d_in[0];
    const float* gnw = (const float*)d_in[1];
    const float* gnb = (const float*)d_in[2];
    const float* wq  = (const float*)d_in[3];
    const float* bq  = (const float*)d_in[4];
    const float* wk  = (const float*)d_in[5];
    const float* bk  = (const float*)d_in[6];
    const float* wv  = (const float*)d_in[7];
    const float* bv  = (const float*)d_in[8];
    const float* wp  = (const float*)d_in[9];
    const float* bp  = (const float*)d_in[10];
    float* out = (float*)d_out;

    int B = in_sizes[0] / (C_DIM * N_DIM);
    if (B < 1) B = 1;
    if (B > MAXB) B = MAXB;

    __half *xs, *qs, *ks, *vs, *vps, *wh, *wl, *attn, *ps;
    cudaGetSymbolAddress((void**)&xs,  g_xs);
    cudaGetSymbolAddress((void**)&qs,  g_qs);
    cudaGetSymbolAddress((void**)&ks,  g_ks);
    cudaGetSymbolAddress((void**)&vs,  g_vs);
    cudaGetSymbolAddress((void**)&vps, g_vps);
    cudaGetSymbolAddress((void**)&wh,  g_wh);
    cudaGetSymbolAddress((void**)&wl,  g_wl);
    cudaGetSymbolAddress((void**)&attn, g_attn);
    cudaGetSymbolAddress((void**)&ps,  g_ps);

    const long long CN = (long long)C_DIM * N_DIM;
    const long long NN = (long long)N_DIM * N_DIM;
    const float scale = 1.0f / sqrtf((float)C_DIM);

    int smQKV = 2 * stage_elems(false, false, 1, 0, 32) * 2;
    int smS   = 3 * stage_elems(true,  false, 0, 0, 64) * 2;
    int smVP  = 2 * stage_elems(false, false, 1, 0, 32) * 2;
    int smPV  = 3 * stage_elems(false, true,  0, 0, 64) * 2;
    cudaFuncSetAttribute(pgemm_kernel<false, false, 1, 0, 2, 32, 2>,
                         cudaFuncAttributeMaxDynamicSharedMemorySize, smQKV);
    cudaFuncSetAttribute(pgemm_kernel<true, false, 0, 0, 1, 64, 3>,
                         cudaFuncAttributeMaxDynamicSharedMemorySize, smS);
    cudaFuncSetAttribute(pgemm_kernel<false, false, 1, 0, 1, 32, 2>,
                         cudaFuncAttributeMaxDynamicSharedMemorySize, smVP);
    cudaFuncSetAttribute(pgemm_kernel<false, true, 0, 0, 0, 64, 3>,
                         cudaFuncAttributeMaxDynamicSharedMemorySize, smPV);

    // 1) GroupNorm -> single fp16 xn
    groupnorm_kernel<<<B * 32, 256>>>(x, gnw, gnb, xs);

    // 2) Split all 4 weight matrices in one launch
    {
        int n4 = C_DIM * C_DIM / 4;
        dim3 grid((n4 + 255) / 256, 4);
        split4_kernel<<<grid, 256>>>(wq, wk, wv, wp, wh, wl, n4);
    }

    // 3) Fused QKV projection (2-term: W split, x single) -> single fp16 q/k/v
    {
        dim3 grid(N_DIM / 128, 12, B);
        pgemm_kernel<false, false, 1, 0, 2, 32, 2><<<grid, 256, smQKV>>>(
            wh, wl, xs, (const __half*)0,
            (float*)0, (__half*)0, qs, ks, vs,
            C_DIM, C_DIM, N_DIM, N_DIM, 0, CN, CN,
            bq, bk, bv, (const float*)0, 0, 1.0f);
    }

    // 4) Scores (1-term, BK=64, 3-stage, DB): attn = fp16(scale * q^T k)
    {
        dim3 grid(N_DIM / 128, N_DIM / 128, B);
        pgemm_kernel<true, false, 0, 0, 1, 64, 3><<<grid, 256, smS>>>(
            qs, (const __half*)0, ks, (const __half*)0,
            (float*)0, attn, (__half*)0, (__half*)0, (__half*)0,
            C_DIM, N_DIM, N_DIM, N_DIM, CN, CN, NN,
            (const float*)0, (const float*)0, (const float*)0,
            (const float*)0, 0, scale);
    }

    // 5) V' = Wp . v  (2-term: Wp split, v single) -> single fp16
    {
        long long CC = (long long)C_DIM * C_DIM;
        dim3 grid(N_DIM / 128, C_DIM / 128, B);
        pgemm_kernel<false, false, 1, 0, 1, 32, 2><<<grid, 256, smVP>>>(
            wh + 3 * CC, wl + 3 * CC, vs, (const __half*)0,
            (float*)0, vps, (__half*)0, (__half*)0, (__half*)0,
            C_DIM, C_DIM, N_DIM, N_DIM, 0, CN, CN,
            (const float*)0, (const float*)0, (const float*)0,
            (const float*)0, 0, 1.0f);
    }

    // 6) Softmax -> fp16 P
    softmax_kernel<<<B * N_DIM, 256>>>(attn, ps);

    // 7) Final (1-term, BK=64, 3-stage, DB): out = V'.P + bp + x
    {
        dim3 grid(N_DIM / 128, C_DIM / 128, B);
        pgemm_kernel<false, true, 0, 0, 0, 64, 3><<<grid, 256, smPV>>>(
            vps, (const __half*)0, ps, (const __half*)0,
            out, (__half*)0, (__half*)0, (__half*)0, (__half*)0,
            N_DIM, N_DIM, N_DIM, N_DIM, CN, NN, CN,
            bp, (const float*)0, (const float*)0, x, CN, 1.0f);
    }
}

// round 14
// speedup vs baseline: 1.1513x; 1.1513x over previous
#include <cuda_runtime.h>
#include <cuda_fp16.h>
#include <stdint.h>
#include <math.h>

typedef unsigned int u32;

#define C_DIM 512
#define N_DIM 4096
#define MAXB  4

// -------- scratch (__device__ globals) --------------------------------------
__device__ __half g_xs[MAXB * C_DIM * N_DIM];   // xn single fp16
__device__ __half g_qs[MAXB * C_DIM * N_DIM];   // q single fp16
__device__ __half g_ks[MAXB * C_DIM * N_DIM];   // k single fp16
__device__ __half g_vs[MAXB * C_DIM * N_DIM];   // v single fp16
__device__ __half g_vps[MAXB * C_DIM * N_DIM];  // V' = Wp.v single fp16
__device__ __half g_ws[4 * C_DIM * C_DIM];      // weights single fp16 (q,k,v,p)
__device__ __half g_attn[MAXB * (size_t)N_DIM * N_DIM];  // S fp16 (134 MB)
__device__ __half g_ps[MAXB * (size_t)N_DIM * N_DIM];    // P fp16 (134 MB)

// ============================================================================
// Helpers
// ============================================================================
__device__ __forceinline__ void single_store2(__half* C, size_t o, float x, float y)
{
    __half2 t(__float2half(x), __float2half(y));
    *(u32*)&C[o] = *(u32*)&t;
}

__device__ __forceinline__ u32 saddr(const void* p)
{
    return (u32)__cvta_generic_to_shared(p);
}

__device__ __forceinline__ void cp16(u32 dst, const void* src)
{
    asm volatile("cp.async.cg.shared.global [%0], [%1], 16;\n" :: "r"(dst), "l"(src));
}
__device__ __forceinline__ void cp_commit()
{
    asm volatile("cp.async.commit_group;\n");
}
template <int NN_>
__device__ __forceinline__ void cp_wait()
{
    asm volatile("cp.async.wait_group %0;\n" :: "n"(NN_));
}

__device__ __forceinline__ void ldsm4(u32* r, u32 a)
{
    asm volatile("ldmatrix.sync.aligned.m8n8.x4.shared.b16 {%0,%1,%2,%3}, [%4];\n"
        : "=r"(r[0]), "=r"(r[1]), "=r"(r[2]), "=r"(r[3]) : "r"(a));
}
__device__ __forceinline__ void ldsm4t(u32* r, u32 a)
{
    asm volatile("ldmatrix.sync.aligned.m8n8.x4.trans.shared.b16 {%0,%1,%2,%3}, [%4];\n"
        : "=r"(r[0]), "=r"(r[1]), "=r"(r[2]), "=r"(r[3]) : "r"(a));
}
__device__ __forceinline__ void mma_f16(float* c, const u32* a, u32 b0, u32 b1)
{
    asm volatile(
        "mma.sync.aligned.m16n8k16.row.col.f32.f16.f16.f32 "
        "{%0,%1,%2,%3}, {%4,%5,%6,%7}, {%8,%9}, {%0,%1,%2,%3};\n"
        : "+f"(c[0]), "+f"(c[1]), "+f"(c[2]), "+f"(c[3])
        : "r"(a[0]), "r"(a[1]), "r"(a[2]), "r"(a[3]), "r"(b0), "r"(b1));
}

// ============================================================================
// fp32 -> single fp16, all 4 weight matrices in one launch (grid.y = matrix)
// ============================================================================
__global__ void convert4_kernel(const float* __restrict__ wq,
                                const float* __restrict__ wk,
                                const float* __restrict__ wv,
                                const float* __restrict__ wp,
                                __half* __restrict__ h, int n4)
{
    int i = blockIdx.x * blockDim.x + threadIdx.x;
    if (i >= n4) return;
    int sel = blockIdx.y;
    const float* in = (sel == 0) ? wq : (sel == 1) ? wk : (sel == 2) ? wv : wp;
    size_t off = (size_t)sel * n4 * 4;
    float4 v = ((const float4*)in)[i];
    single_store2(h + off, (size_t)i * 4,     v.x, v.y);
    single_store2(h + off, (size_t)i * 4 + 2, v.z, v.w);
}

// ============================================================================
// GroupNorm: 32 groups, 16 ch/group, eps=1e-5; writes single fp16
// ============================================================================
__global__ void groupnorm_kernel(const float* __restrict__ x,
                                 const float* __restrict__ w,
                                 const float* __restrict__ b,
                                 __half* __restrict__ os)
{
    const int CPG = 16;
    const int CNT = CPG * N_DIM;
    int bg = blockIdx.x;
    int g  = bg & 31;
    int bb = bg >> 5;
    size_t base = ((size_t)bb * C_DIM + (size_t)g * CPG) * N_DIM;
    const float4* x4 = (const float4*)(x + base);
    int tid = threadIdx.x;

    float s = 0.f, ss = 0.f;
    for (int i = tid; i < CNT / 4; i += blockDim.x) {
        float4 v = x4[i];
        s  += v.x + v.y + v.z + v.w;
        ss += v.x * v.x + v.y * v.y + v.z * v.z + v.w * v.w;
    }
    __shared__ float rs[8], rss[8];
    #pragma unroll
    for (int o = 16; o; o >>= 1) {
        s  += __shfl_xor_sync(0xffffffffu, s,  o);
        ss += __shfl_xor_sync(0xffffffffu, ss, o);
    }
    int wid = tid >> 5;
    int lid = tid & 31;
    if (lid == 0) { rs[wid] = s; rss[wid] = ss; }
    __syncthreads();
    if (tid == 0) {
        float ts = 0.f, tss = 0.f;
        int nw = blockDim.x >> 5;
        for (int i = 0; i < nw; i++) { ts += rs[i]; tss += rss[i]; }
        rs[0] = ts; rss[0] = tss;
    }
    __syncthreads();
    float mu   = rs[0] / (float)CNT;
    float var  = rss[0] / (float)CNT - mu * mu;
    float rsig = rsqrtf(var + 1e-5f);

    for (int i = tid; i < CNT / 4; i += blockDim.x) {
        int c = g * CPG + (i >> 10);
        float sc = w[c] * rsig;
        float sh = b[c] - mu * sc;
        float4 v = x4[i];
        size_t o = base + (size_t)i * 4;
        single_store2(os, o,     v.x * sc + sh, v.y * sc + sh);
        single_store2(os, o + 2, v.z * sc + sh, v.w * sc + sh);
    }
}

// ============================================================================
// Pipelined fp16 tensor-core GEMM (cp.async, NST stages, 2 CTAs/SM).
//   C[m,n] = alpha * sum_k A(m,k)*B(k,n)   (pure single-fp16, 1 MMA/tile)
//   TA/TB: storage orientation. BK: 32 or 64. NST: pipeline stages.
//   OMODE: 0 = fp32 out (+row bias, +res)
//          1 = single fp16 out (Ch) (+row bias)
//          2 = fused-QKV routing (blockIdx.y: 0-3=q,4-7=k,8-11=v; single out)
// Conflict-free smem strides: narrow rows 56 (BK32) / 72 (BK64); wide rows 136.
// ============================================================================
template <bool TA, bool TB, int OMODE, int BK, int NST>
__global__ __launch_bounds__(256, 2)
void pgemm_kernel(const __half* __restrict__ Ag,
                  const __half* __restrict__ Bg,
                  float* __restrict__ Cf,
                  __half* __restrict__ Ch,
                  __half* __restrict__ Qs,
                  __half* __restrict__ Ks,
                  __half* __restrict__ Vs,
                  int K, int lda, int ldb, int ldc,
                  long long sA, long long sB, long long sC,
                  const float* __restrict__ bias,
                  const float* __restrict__ bias2,
                  const float* __restrict__ bias3,
                  const float* __restrict__ res, long long sRes,
                  float alpha)
{
    const int PAD = (BK == 32) ? 56 : (BK + 8);
    const int AST = TA ? 136 : PAD;
    const int BST = TB ? PAD : 136;
    const int ASZ = TA ? (BK * AST) : (128 * AST);
    const int BSZ = TB ? (128 * BST) : (BK * BST);
    const int STAGE = ASZ + BSZ;
    const int KD = BK / 8;
    const int RIT = BK / 16;
    const int NKS = BK / 16;

    extern __shared__ __align__(16) char smraw[];
    __half* sm = (__half*)smraw;

    int z = blockIdx.z;
    Ag += (long long)z * sA;
    Bg += (long long)z * sB;

    int sel = 0;
    int m0;
    if (OMODE == 2) {
        sel = blockIdx.y >> 2;
        m0  = (blockIdx.y & 3) * 128;
        Ag += (long long)sel * C_DIM * C_DIM;
        Qs += (long long)z * sC;
        Ks += (long long)z * sC;
        Vs += (long long)z * sC;
    } else {
        m0 = blockIdx.y * 128;
        if (OMODE == 1) Ch += (long long)z * sC;
        else            Cf += (long long)z * sC;
        if (OMODE == 0 && res) res += (long long)z * sRes;
    }

    int n0 = blockIdx.x * 128;
    int tid  = threadIdx.x;
    int lane = tid & 31;
    int wid  = tid >> 5;
    int m_w = (wid >> 2) * 64;
    int n_w = (wid & 3) * 32;

    int a_base, b_base;
    if (!TA) {
        a_base = (m_w + (lane & 15)) * AST + ((lane >> 4) * 8);
    } else {
        a_base = (((lane >> 4) & 1) * 8 + (lane & 7)) * AST
               + m_w + ((lane >> 3) & 1) * 8;
    }
    if (!TB) {
        b_base = (((lane >> 3) & 1) * 8 + (lane & 7)) * BST
               + n_w + ((lane >> 4) & 1) * 8;
    } else {
        b_base = (n_w + ((lane >> 4) & 1) * 8 + (lane & 7)) * BST
               + ((lane >> 3) & 1) * 8;
    }

    float c[4][4][4];
    #pragma unroll
    for (int i = 0; i < 4; i++) {
        #pragma unroll
        for (int j = 0; j < 4; j++) {
            #pragma unroll
            for (int t = 0; t < 4; t++) c[i][j][t] = 0.f;
        }
    }

    int KT = K / BK;

    auto load_stage = [&](int st, int k0) {
        __half* sA = sm + st * STAGE;
        __half* sB = sA + ASZ;
        #pragma unroll
        for (int r = 0; r < RIT; r++) {
            int i = tid + r * 256;
            if (!TA) {
                int m  = i / KD;
                int kq = (i % KD) * 8;
                cp16(saddr(sA + m * AST + kq),
                     Ag + (size_t)(m0 + m) * lda + k0 + kq);
            } else {
                int k  = i >> 4;
                int mq = (i & 15) * 8;
                cp16(saddr(sA + k * AST + mq),
                     Ag + (size_t)(k0 + k) * lda + m0 + mq);
            }
            if (!TB) {
                int k  = i >> 4;
                int nq = (i & 15) * 8;
                cp16(saddr(sB + k * BST + nq),
                     Bg + (size_t)(k0 + k) * ldb + n0 + nq);
            } else {
                int n  = i / KD;
                int kq = (i % KD) * 8;
                cp16(saddr(sB + n * BST + kq),
                     Bg + (size_t)(n0 + n) * ldb + k0 + kq);
            }
        }
    };

    #pragma unroll
    for (int s = 0; s < NST - 1; s++) {
        if (s < KT) load_stage(s, s * BK);
        cp_commit();
    }

    for (int kt = 0; kt < KT; kt++) {
        cp_wait<NST - 2>();
        __syncthreads();

        int pf = kt + NST - 1;
        if (pf < KT) load_stage(pf % NST, pf * BK);
        cp_commit();

        int st = kt % NST;
        const __half* pA = sm + st * STAGE;
        const __half* pB = pA + ASZ;

        #pragma unroll
        for (int ks = 0; ks < NKS; ks++) {
            int aoff = a_base + (TA ? ks * 16 * AST : ks * 16);
            int boff = b_base + (TB ? ks * 16 : ks * 16 * BST);

            u32 ah[4][4], bh[2][4];
            #pragma unroll
            for (int mt = 0; mt < 4; mt++) {
                int o = aoff + (TA ? mt * 16 : mt * 16 * AST);
                if (TA) ldsm4t(ah[mt], saddr(pA + o));
                else    ldsm4 (ah[mt], saddr(pA + o));
            }
            #pragma unroll
            for (int p = 0; p < 2; p++) {
                int o = boff + (TB ? p * 16 * BST : p * 16);
                if (TB) ldsm4 (bh[p], saddr(pB + o));
                else    ldsm4t(bh[p], saddr(pB + o));
            }
            #pragma unroll
            for (int mt = 0; mt < 4; mt++) {
                #pragma unroll
                for (int nt = 0; nt < 4; nt++) {
                    int p = nt >> 1;
                    int q = (nt & 1) * 2;
                    mma_f16(c[mt][nt], ah[mt], bh[p][q], bh[p][q + 1]);
                }
            }
        }
        __syncthreads();
    }

    // ---- epilogue ----
    const float* bp_ = bias;
    __half* So = (OMODE == 1) ? Ch : Qs;
    if (OMODE == 2) {
        if (sel == 1)      { bp_ = bias2; So = Ks; }
        else if (sel == 2) { bp_ = bias3; So = Vs; }
    }

    int g  = lane >> 2;
    int tq = lane & 3;
    #pragma unroll
    for (int mt = 0; mt < 4; mt++) {
        int mr0 = m0 + m_w + mt * 16 + g;
        int mr1 = mr0 + 8;
        float b0v = bp_ ? bp_[mr0] : 0.f;
        float b1v = bp_ ? bp_[mr1] : 0.f;
        #pragma unroll
        for (int nt = 0; nt < 4; nt++) {
            int nc = n0 + n_w + nt * 8 + tq * 2;
            size_t o0 = (size_t)mr0 * ldc + nc;
            size_t o1 = (size_t)mr1 * ldc + nc;
            float v00 = c[mt][nt][0] * alpha + b0v;
            float v01 = c[mt][nt][1] * alpha + b0v;
            float v10 = c[mt][nt][2] * alpha + b1v;
            float v11 = c[mt][nt][3] * alpha + b1v;
            if (OMODE == 0) {
                if (res) {
                    float2 r0 = *(const float2*)&res[o0];
                    float2 r1 = *(const float2*)&res[o1];
                    v00 += r0.x; v01 += r0.y;
                    v10 += r1.x; v11 += r1.y;
                }
                float2 w0; w0.x = v00; w0.y = v01;
                float2 w1; w1.x = v10; w1.y = v11;
                *(float2*)&Cf[o0] = w0;
                *(float2*)&Cf[o1] = w1;
            } else {
                single_store2(So, o0, v00, v01);
                single_store2(So, o1, v10, v11);
            }
        }
    }
}

// ============================================================================
// Row softmax over fp16 attn[b,i,:] (4096), writes fp16 P.
// ============================================================================
__global__ void softmax_kernel(const __half* __restrict__ attn,
                               __half* __restrict__ ps)
{
    size_t row = blockIdx.x;
    const uint4* p = (const uint4*)(attn + row * N_DIM);
    uint4* q = (uint4*)(ps + row * N_DIM);
    int tid = threadIdx.x;
    __shared__ float sh[8];

    float v[2][8];
    float mx = -1e30f;
    #pragma unroll
    for (int i = 0; i < 2; i++) {
        uint4 u = p[tid + i * 256];
        u32 w[4] = {u.x, u.y, u.z, u.w};
        #pragma unroll
        for (int j = 0; j < 4; j++) {
            float2 f = __half22float2(*(__half2*)&w[j]);
            v[i][j * 2]     = f.x;
            v[i][j * 2 + 1] = f.y;
            mx = fmaxf(mx, fmaxf(f.x, f.y));
        }
    }
    #pragma unroll
    for (int o = 16; o; o >>= 1) mx = fmaxf(mx, __shfl_xor_sync(0xffffffffu, mx, o));
    if ((tid & 31) == 0) sh[tid >> 5] = mx;
    __syncthreads();
    if (tid == 0) {
        float t = sh[0];
        for (int i = 1; i < 8; i++) t = fmaxf(t, sh[i]);
        sh[0] = t;
    }
    __syncthreads();
    mx = sh[0];
    __syncthreads();

    float sum = 0.f;
    #pragma unroll
    for (int i = 0; i < 2; i++) {
        #pragma unroll
        for (int j = 0; j < 8; j++) {
            v[i][j] = __expf(v[i][j] - mx);
            sum += v[i][j];
        }
    }
    #pragma unroll
    for (int o = 16; o; o >>= 1) sum += __shfl_xor_sync(0xffffffffu, sum, o);
    if ((tid & 31) == 0) sh[tid >> 5] = sum;
    __syncthreads();
    if (tid == 0) {
        float t = 0.f;
        for (int i = 0; i < 8; i++) t += sh[i];
        sh[0] = t;
    }
    __syncthreads();
    float inv = 1.f / sh[0];

    #pragma unroll
    for (int i = 0; i < 2; i++) {
        uint4 u;
        u32* w = (u32*)&u;
        #pragma unroll
        for (int j = 0; j < 4; j++) {
            __half2 t(__float2half(v[i][j * 2] * inv),
                      __float2half(v[i][j * 2 + 1] * inv));
            w[j] = *(u32*)&t;
        }
        q[tid + i * 256] = u;
    }
}

// ============================================================================
// Host launcher
// ============================================================================
static int stage_elems(bool ta, bool tb, int bk)
{
    int pad = (bk == 32) ? 56 : (bk + 8);
    int AST = ta ? 136 : pad;
    int BST = tb ? pad : 136;
    int ASZ = ta ? (bk * AST) : (128 * AST);
    int BSZ = tb ? (128 * BST) : (bk * BST);
    return ASZ + BSZ;
}

extern "C" void kernel_launch(void* const* d_in, const int* in_sizes, int n_in,
                              void* d_out, int out_size)
{
    const float* x   = (const float*)d_in[0];
    const float* gnw = (const float*)d_in[1];
    const float* gnb = (const float*)d_in[2];
    const float* wq  = (const float*)d_in[3];
    const float* bq  = (const float*)d_in[4];
    const float* wk  = (const float*)d_in[5];
    const float* bk  = (const float*)d_in[6];
    const float* wv  = (const float*)d_in[7];
    const float* bv  = (const float*)d_in[8];
    const float* wp  = (const float*)d_in[9];
    const float* bp  = (const float*)d_in[10];
    float* out = (float*)d_out;

    int B = in_sizes[0] / (C_DIM * N_DIM);
    if (B < 1) B = 1;
    if (B > MAXB) B = MAXB;

    __half *xs, *qs, *ks, *vs, *vps, *ws, *attn, *ps;
    cudaGetSymbolAddress((void**)&xs,  g_xs);
    cudaGetSymbolAddress((void**)&qs,  g_qs);
    cudaGetSymbolAddress((void**)&ks,  g_ks);
    cudaGetSymbolAddress((void**)&vs,  g_vs);
    cudaGetSymbolAddress((void**)&vps, g_vps);
    cudaGetSymbolAddress((void**)&ws,  g_ws);
    cudaGetSymbolAddress((void**)&attn, g_attn);
    cudaGetSymbolAddress((void**)&ps,  g_ps);

    const long long CN = (long long)C_DIM * N_DIM;
    const long long NN = (long long)N_DIM * N_DIM;
    const float scale = 1.0f / sqrtf((float)C_DIM);

    int smQKV = 2 * stage_elems(false, false, 32) * 2;
    int smS   = 3 * stage_elems(true,  false, 64) * 2;
    int smPV  = 3 * stage_elems(false, true,  64) * 2;
    cudaFuncSetAttribute(pgemm_kernel<false, false, 2, 32, 2>,
                         cudaFuncAttributeMaxDynamicSharedMemorySize, smQKV);
    cudaFuncSetAttribute(pgemm_kernel<true, false, 1, 64, 3>,
                         cudaFuncAttributeMaxDynamicSharedMemorySize, smS);
    cudaFuncSetAttribute(pgemm_kernel<false, false, 1, 32, 2>,
                         cudaFuncAttributeMaxDynamicSharedMemorySize, smQKV);
    cudaFuncSetAttribute(pgemm_kernel<false, true, 0, 64, 3>,
                         cudaFuncAttributeMaxDynamicSharedMemorySize, smPV);

    // 1) GroupNorm -> single fp16 xn
    groupnorm_kernel<<<B * 32, 256>>>(x, gnw, gnb, xs);

    // 2) Convert all 4 weight matrices to single fp16 in one launch
    {
        int n4 = C_DIM * C_DIM / 4;
        dim3 grid((n4 + 255) / 256, 4);
        convert4_kernel<<<grid, 256>>>(wq, wk, wv, wp, ws, n4);
    }

    // 3) Fused QKV projection (1-term) -> single fp16 q/k/v
    {
        dim3 grid(N_DIM / 128, 12, B);
        pgemm_kernel<false, false, 2, 32, 2><<<grid, 256, smQKV>>>(
            ws, xs,
            (float*)0, (__half*)0, qs, ks, vs,
            C_DIM, C_DIM, N_DIM, N_DIM, 0, CN, CN,
            bq, bk, bv, (const float*)0, 0, 1.0f);
    }

    // 4) Scores (1-term, BK=64, 3-stage): attn = fp16(scale * q^T k)
    {
        dim3 grid(N_DIM / 128, N_DIM / 128, B);
        pgemm_kernel<true, false, 1, 64, 3><<<grid, 256, smS>>>(
            qs, ks,
            (float*)0, attn, (__half*)0, (__half*)0, (__half*)0,
            C_DIM, N_DIM, N_DIM, N_DIM, CN, CN, NN,
            (const float*)0, (const float*)0, (const float*)0,
            (const float*)0, 0, scale);
    }

    // 5) V' = Wp . v  (1-term) -> single fp16
    {
        long long CC = (long long)C_DIM * C_DIM;
        dim3 grid(N_DIM / 128, C_DIM / 128, B);
        pgemm_kernel<false, false, 1, 32, 2><<<grid, 256, smQKV>>>(
            ws + 3 * CC, vs,
            (float*)0, vps, (__half*)0, (__half*)0, (__half*)0,
            C_DIM, C_DIM, N_DIM, N_DIM, 0, CN, CN,
            (const float*)0, (const float*)0, (const float*)0,
            (const float*)0, 0, 1.0f);
    }

    // 6) Softmax -> fp16 P
    softmax_kernel<<<B * N_DIM, 256>>>(attn, ps);

    // 7) Final (1-term, BK=64, 3-stage): out = V'.P + bp + x
    {
        dim3 grid(N_DIM / 128, C_DIM / 128, B);
        pgemm_kernel<false, true, 0, 64, 3><<<grid, 256, smPV>>>(
            vps, ps,
            out, (__half*)0, (__half*)0, (__half*)0, (__half*)0,
            N_DIM, N_DIM, N_DIM, N_DIM, CN, NN, CN,
            bp, (const float*)0, (const float*)0, x, CN, 1.0f);
    }
}